// round 1
// baseline (speedup 1.0000x reference)
#include <cuda_runtime.h>
#include <cstdint>
#include <cstddef>

#define S_LEN  4096
#define DMODEL 512
#define NHEADS 8
#define HDK    64

// Scratch (allocation-free rule: __device__ globals)
__device__ float g_q[S_LEN * DMODEL];
__device__ float g_k[S_LEN * DMODEL];
__device__ float g_v[S_LEN * DMODEL];
__device__ float g_attn[S_LEN * DMODEL];

// ---------------------------------------------------------------------------
// GEMM-NT:  C[M=4096, N=512] = A[M,512] * B[N,512]^T + bias[N]
// BM=64 BN=64 BK=32, 256 threads, 4x4 micro-tile, smem operands transposed
// so compute reads are 2x LDS.128 per 16 FMA.
// ---------------------------------------------------------------------------
__device__ __forceinline__ void gemm_tile(
    const float* __restrict__ A, const float* __restrict__ B,
    const float* __restrict__ bias, float* __restrict__ C)
{
    __shared__ float As[32][68];
    __shared__ float Bs[32][68];

    const int tid = threadIdx.x;
    const int m0 = blockIdx.y << 6;
    const int n0 = blockIdx.x << 6;
    const int ty = tid >> 4;   // 0..15
    const int tx = tid & 15;   // 0..15

    float acc[4][4] = {};

    for (int k0 = 0; k0 < 512; k0 += 32) {
#pragma unroll
        for (int r = 0; r < 2; r++) {
            int idx  = tid + (r << 8);     // 0..511
            int row  = idx >> 3;           // 0..63
            int kk4  = (idx & 7) << 2;     // 0,4,...,28
            float4 a = *(const float4*)&A[(size_t)(m0 + row) * 512 + k0 + kk4];
            As[kk4 + 0][row] = a.x; As[kk4 + 1][row] = a.y;
            As[kk4 + 2][row] = a.z; As[kk4 + 3][row] = a.w;
            float4 b = *(const float4*)&B[(size_t)(n0 + row) * 512 + k0 + kk4];
            Bs[kk4 + 0][row] = b.x; Bs[kk4 + 1][row] = b.y;
            Bs[kk4 + 2][row] = b.z; Bs[kk4 + 3][row] = b.w;
        }
        __syncthreads();

#pragma unroll
        for (int kk = 0; kk < 32; kk++) {
            float4 a4 = *(const float4*)&As[kk][ty << 2];
            float4 b4 = *(const float4*)&Bs[kk][tx << 2];
            float av[4] = {a4.x, a4.y, a4.z, a4.w};
            float bw[4] = {b4.x, b4.y, b4.z, b4.w};
#pragma unroll
            for (int i = 0; i < 4; i++)
#pragma unroll
                for (int j = 0; j < 4; j++)
                    acc[i][j] = fmaf(av[i], bw[j], acc[i][j]);
        }
        __syncthreads();
    }

    float4 bb = *(const float4*)&bias[n0 + (tx << 2)];
#pragma unroll
    for (int i = 0; i < 4; i++) {
        float4 o = { acc[i][0] + bb.x, acc[i][1] + bb.y,
                     acc[i][2] + bb.z, acc[i][3] + bb.w };
        *(float4*)&C[(size_t)(m0 + (ty << 2) + i) * 512 + n0 + (tx << 2)] = o;
    }
}

__global__ __launch_bounds__(256) void qkv_kernel(
    const float* __restrict__ x,
    const float* __restrict__ wq, const float* __restrict__ bq,
    const float* __restrict__ wk, const float* __restrict__ bk,
    const float* __restrict__ wv, const float* __restrict__ bv)
{
    const float* W; const float* bvec; float* C;
    if (blockIdx.z == 0)      { W = wq; bvec = bq; C = g_q; }
    else if (blockIdx.z == 1) { W = wk; bvec = bk; C = g_k; }
    else                      { W = wv; bvec = bv; C = g_v; }
    gemm_tile(x, W, bvec, C);
}

__global__ __launch_bounds__(256) void dense_kernel(
    const float* __restrict__ W, const float* __restrict__ b,
    float* __restrict__ out)
{
    gemm_tile(g_attn, W, b, out);
}

// ---------------------------------------------------------------------------
// Flash attention, fp32. One CTA = one (64-query-block, head).
// BQ = BKtile = 64, online softmax. Mask read directly from global (L2-resident).
// smem: Qs/Ks transposed [d][row] for float4 S-compute; Vs direct [row][d];
// Ps staged for the PV product.
// ---------------------------------------------------------------------------
#define ATT_SMEM (4 * 64 * 68 * 4)

__global__ __launch_bounds__(256) void attn_kernel(const int* __restrict__ mask)
{
    extern __shared__ float sm[];
    float (*Qs)[68] = reinterpret_cast<float(*)[68]>(sm);
    float (*Ks)[68] = reinterpret_cast<float(*)[68]>(sm + 64 * 68);
    float (*Vs)[68] = reinterpret_cast<float(*)[68]>(sm + 2 * 64 * 68);
    float (*Ps)[68] = reinterpret_cast<float(*)[68]>(sm + 3 * 64 * 68);

    const int tid = threadIdx.x;
    const int ty  = tid >> 4;
    const int tx  = tid & 15;
    const int q0  = blockIdx.x << 6;
    const int h   = blockIdx.y;

    const float* __restrict__ Qg = g_q + (size_t)h * S_LEN * HDK;
    const float* __restrict__ Kg = g_k + (size_t)h * S_LEN * HDK;
    const float* __restrict__ Vg = g_v + (size_t)h * S_LEN * HDK;

    // Load Q tile once, transposed: Qs[d][row]
#pragma unroll
    for (int r = 0; r < 4; r++) {
        int idx = tid + (r << 8);          // 0..1023
        int row = idx >> 4;                // 0..63
        int d4  = (idx & 15) << 2;
        float4 q = *(const float4*)&Qg[(size_t)((q0 + row) << 6) + d4];
        Qs[d4 + 0][row] = q.x; Qs[d4 + 1][row] = q.y;
        Qs[d4 + 2][row] = q.z; Qs[d4 + 3][row] = q.w;
    }

    float o[4][4] = {};
    float mrow[4], lrow[4];
#pragma unroll
    for (int i = 0; i < 4; i++) { mrow[i] = -1e30f; lrow[i] = 0.f; }

    for (int k0 = 0; k0 < S_LEN; k0 += 64) {
        // Load K (transposed) + V (direct)
#pragma unroll
        for (int r = 0; r < 4; r++) {
            int idx = tid + (r << 8);
            int row = idx >> 4;
            int d4  = (idx & 15) << 2;
            float4 kq = *(const float4*)&Kg[(size_t)((k0 + row) << 6) + d4];
            Ks[d4 + 0][row] = kq.x; Ks[d4 + 1][row] = kq.y;
            Ks[d4 + 2][row] = kq.z; Ks[d4 + 3][row] = kq.w;
            float4 vv = *(const float4*)&Vg[(size_t)((k0 + row) << 6) + d4];
            *(float4*)&Vs[row][d4] = vv;
        }
        __syncthreads();

        // S = Q K^T
        float s[4][4] = {};
#pragma unroll
        for (int kk = 0; kk < 64; kk++) {
            float4 a4 = *(const float4*)&Qs[kk][ty << 2];
            float4 b4 = *(const float4*)&Ks[kk][tx << 2];
            float av[4] = {a4.x, a4.y, a4.z, a4.w};
            float bw[4] = {b4.x, b4.y, b4.z, b4.w};
#pragma unroll
            for (int i = 0; i < 4; i++)
#pragma unroll
                for (int j = 0; j < 4; j++)
                    s[i][j] = fmaf(av[i], bw[j], s[i][j]);
        }

        // scale + mask + online softmax
#pragma unroll
        for (int i = 0; i < 4; i++) {
            const int4 m4 = *(const int4*)&mask[(size_t)(q0 + (ty << 2) + i) * S_LEN
                                                + k0 + (tx << 2)];
            s[i][0] = fmaf(s[i][0], 0.125f, (float)m4.x * -1e9f);
            s[i][1] = fmaf(s[i][1], 0.125f, (float)m4.y * -1e9f);
            s[i][2] = fmaf(s[i][2], 0.125f, (float)m4.z * -1e9f);
            s[i][3] = fmaf(s[i][3], 0.125f, (float)m4.w * -1e9f);

            float lm = fmaxf(fmaxf(s[i][0], s[i][1]), fmaxf(s[i][2], s[i][3]));
#pragma unroll
            for (int off = 8; off; off >>= 1)
                lm = fmaxf(lm, __shfl_xor_sync(0xffffffffu, lm, off));
            float mn = fmaxf(mrow[i], lm);
            float alpha = __expf(mrow[i] - mn);
            mrow[i] = mn;

            float p0 = __expf(s[i][0] - mn), p1 = __expf(s[i][1] - mn);
            float p2 = __expf(s[i][2] - mn), p3 = __expf(s[i][3] - mn);
            float ls = (p0 + p1) + (p2 + p3);
#pragma unroll
            for (int off = 8; off; off >>= 1)
                ls += __shfl_xor_sync(0xffffffffu, ls, off);
            lrow[i] = lrow[i] * alpha + ls;

            o[i][0] *= alpha; o[i][1] *= alpha; o[i][2] *= alpha; o[i][3] *= alpha;

            float4 pv = {p0, p1, p2, p3};
            *(float4*)&Ps[(ty << 2) + i][tx << 2] = pv;
        }
        __syncthreads();

        // O += P V
#pragma unroll
        for (int kk = 0; kk < 64; kk += 4) {
            float pa[4][4], va[4][4];
#pragma unroll
            for (int i = 0; i < 4; i++) {
                float4 p = *(const float4*)&Ps[(ty << 2) + i][kk];
                pa[i][0] = p.x; pa[i][1] = p.y; pa[i][2] = p.z; pa[i][3] = p.w;
            }
#pragma unroll
            for (int c = 0; c < 4; c++) {
                float4 v = *(const float4*)&Vs[kk + c][tx << 2];
                va[c][0] = v.x; va[c][1] = v.y; va[c][2] = v.z; va[c][3] = v.w;
            }
#pragma unroll
            for (int i = 0; i < 4; i++)
#pragma unroll
                for (int j = 0; j < 4; j++) {
                    o[i][j] = fmaf(pa[i][0], va[0][j], o[i][j]);
                    o[i][j] = fmaf(pa[i][1], va[1][j], o[i][j]);
                    o[i][j] = fmaf(pa[i][2], va[2][j], o[i][j]);
                    o[i][j] = fmaf(pa[i][3], va[3][j], o[i][j]);
                }
        }
        __syncthreads();
    }

    // Epilogue: write [S, H*DK] layout (= transpose(0,2,1,3).reshape)
#pragma unroll
    for (int i = 0; i < 4; i++) {
        float inv = 1.0f / lrow[i];
        float4 ov = { o[i][0] * inv, o[i][1] * inv, o[i][2] * inv, o[i][3] * inv };
        *(float4*)&g_attn[(size_t)(q0 + (ty << 2) + i) * DMODEL
                          + h * HDK + (tx << 2)] = ov;
    }
}

// ---------------------------------------------------------------------------
extern "C" void kernel_launch(void* const* d_in, const int* in_sizes, int n_in,
                              void* d_out, int out_size)
{
    const float* x    = (const float*)d_in[0];
    const int*   mask = (const int*)  d_in[1];
    const float* wq   = (const float*)d_in[2];
    const float* bq   = (const float*)d_in[3];
    const float* wk   = (const float*)d_in[4];
    const float* bk   = (const float*)d_in[5];
    const float* wv   = (const float*)d_in[6];
    const float* bv   = (const float*)d_in[7];
    const float* wd   = (const float*)d_in[8];
    const float* bd   = (const float*)d_in[9];
    float* out = (float*)d_out;

    // Opt in to >48KB dynamic smem (host-side attribute, not a stream op;
    // safe under graph capture, called unconditionally for determinism).
    cudaFuncSetAttribute(attn_kernel,
                         cudaFuncAttributeMaxDynamicSharedMemorySize, ATT_SMEM);

    qkv_kernel<<<dim3(8, 64, 3), 256>>>(x, wq, bq, wk, bk, wv, bv);
    attn_kernel<<<dim3(64, NHEADS), 256, ATT_SMEM>>>(mask);
    dense_kernel<<<dim3(8, 64), 256>>>(wd, bd, out);
}